// round 3
// baseline (speedup 1.0000x reference)
#include <cuda_runtime.h>
#include <math.h>

// Problem constants
#define BB 2048     // batch (samples == queries)
#define RR 64       // receptors
#define QT 16       // query tiles for KDE kernel
#define QTH 128     // threads per KDE block (queries per tile)
#define CB 32       // row-chunks for covariance Gram
#define CROWS 64    // rows per covariance chunk (CB*CROWS == BB)

// -------- device scratch (static: no allocations allowed) --------
__device__ float g_scaled[RR * BB];      // column-major, value * invh * sqrt(0.5*log2e)
__device__ float g_dnorm[RR];            // invh / (B * sqrt(2*pi))
__device__ float g_mean[RR];
__device__ float g_ent_partial[QT * RR]; // per-(qtile, r) sum of log(density+eps)
__device__ float g_gram[CB * RR * RR];   // partial centered Gram per row-chunk

// Hardware exp2: single MUFU.EX2, flush-to-zero on tiny results (harmless here).
__device__ __forceinline__ float ex2(float x) {
    float y;
    asm("ex2.approx.ftz.f32 %0, %1;" : "=f"(y) : "f"(x));
    return y;
}

// ---------------------------------------------------------------------------
// Stage 1: per-column mean, std (ddof=1), bandwidth h; write scaled column-
// major copy of activity so the KDE inner loop is FADD+FMUL+EX2+FADD only.
// ---------------------------------------------------------------------------
__global__ void stats_kernel(const float* __restrict__ act) {
    __shared__ float sh[BB];
    __shared__ float red[256];
    const int r = blockIdx.x;
    const int tid = threadIdx.x;   // 256 threads

    float s = 0.f;
    for (int i = tid; i < BB; i += 256) {
        float v = act[i * RR + r];
        sh[i] = v;
        s += v;
    }
    red[tid] = s;
    __syncthreads();
    for (int o = 128; o > 0; o >>= 1) {
        if (tid < o) red[tid] += red[tid + o];
        __syncthreads();
    }
    const float mean = red[0] * (1.0f / BB);
    __syncthreads();

    float ss = 0.f;
    for (int i = tid; i < BB; i += 256) {
        float d = sh[i] - mean;
        ss += d * d;
    }
    red[tid] = ss;
    __syncthreads();
    for (int o = 128; o > 0; o >>= 1) {
        if (tid < o) red[tid] += red[tid + o];
        __syncthreads();
    }
    const float var  = red[0] * (1.0f / (BB - 1));
    const float stdv = sqrtf(var);
    // BANDWIDTH_FACTOR * std * B^(-0.2);  2048^(-0.2) = 0.21763764
    const float h    = fmaxf(1.06f * stdv * 0.21763764f, 1e-4f);
    const float invh = 1.0f / h;

    // sqrt(0.5 * log2(e)) so exp(-0.5*u^2) == 2^{-(u')^2} with u' = u*KS
    const float KS = 0.84932184f;
    const float k  = invh * KS;
    for (int i = tid; i < BB; i += 256)
        g_scaled[r * BB + i] = sh[i] * k;

    if (tid == 0) {
        g_dnorm[r] = invh * (1.0f / (2048.0f * 2.5066282746310002f)); // invh/(B*sqrt(2pi))
        g_mean[r]  = mean;
    }
}

// ---------------------------------------------------------------------------
// Stage 2: KDE densities + per-block sum of log(density + eps).
// grid (QT, RR), QTH threads; each thread owns one query, loops all samples
// from shared (broadcast reads). MUFU-bound by design.
// ---------------------------------------------------------------------------
__global__ void kde_kernel() {
    __shared__ float sh[BB];
    __shared__ float red[QTH];
    const int r   = blockIdx.y;
    const int qt  = blockIdx.x;
    const int tid = threadIdx.x;  // QTH = 128

    const float* __restrict__ col = g_scaled + r * BB;
    for (int i = tid; i < BB; i += QTH) sh[i] = col[i];
    __syncthreads();

    const int   q  = qt * QTH + tid;
    const float aq = sh[q];

    float a0 = 0.f, a1 = 0.f, a2 = 0.f, a3 = 0.f;
    float a4 = 0.f, a5 = 0.f, a6 = 0.f, a7 = 0.f;

    const float4* __restrict__ s4 = reinterpret_cast<const float4*>(sh);
    #pragma unroll 1
    for (int c = 0; c < BB / 8; ++c) {
        const float4 v0 = s4[2 * c + 0];
        const float4 v1 = s4[2 * c + 1];
        float u;
        u = aq - v0.x; a0 += ex2(-u * u);
        u = aq - v0.y; a1 += ex2(-u * u);
        u = aq - v0.z; a2 += ex2(-u * u);
        u = aq - v0.w; a3 += ex2(-u * u);
        u = aq - v1.x; a4 += ex2(-u * u);
        u = aq - v1.y; a5 += ex2(-u * u);
        u = aq - v1.z; a6 += ex2(-u * u);
        u = aq - v1.w; a7 += ex2(-u * u);
    }
    const float acc  = ((a0 + a1) + (a2 + a3)) + ((a4 + a5) + (a6 + a7));
    const float dens = acc * g_dnorm[r];
    const float lg   = logf(dens + 1e-8f);

    red[tid] = lg;
    __syncthreads();
    for (int o = QTH / 2; o > 0; o >>= 1) {
        if (tid < o) red[tid] += red[tid + o];
        __syncthreads();
    }
    if (tid == 0) g_ent_partial[qt * RR + r] = red[0];
}

// ---------------------------------------------------------------------------
// Stage 3: partial centered Gram (covariance numerator), tiled over rows.
// Each block handles CROWS rows; 16x16 threads each produce a 4x4 output tile.
// ---------------------------------------------------------------------------
__global__ void cov_kernel(const float* __restrict__ act) {
    __shared__ float sh[CROWS * RR];   // centered row tile: 64 x 64
    __shared__ float shm[RR];
    const int b   = blockIdx.x;
    const int tid = threadIdx.x;       // 256 threads

    if (tid < RR) shm[tid] = g_mean[tid];
    __syncthreads();

    const int base = b * CROWS * RR;
    for (int i = tid; i < CROWS * RR; i += 256)
        sh[i] = act[base + i] - shm[i & (RR - 1)];
    __syncthreads();

    const int ti = tid & 15;   // column-group i
    const int tj = tid >> 4;   // column-group j
    float acc[4][4];
    #pragma unroll
    for (int y = 0; y < 4; ++y)
        #pragma unroll
        for (int x = 0; x < 4; ++x) acc[y][x] = 0.f;

    const float4* __restrict__ s4 = reinterpret_cast<const float4*>(sh);
    for (int s = 0; s < CROWS; ++s) {
        const float4 ai = s4[s * 16 + ti];
        const float4 aj = s4[s * 16 + tj];
        const float av[4] = { ai.x, ai.y, ai.z, ai.w };
        const float bv[4] = { aj.x, aj.y, aj.z, aj.w };
        #pragma unroll
        for (int y = 0; y < 4; ++y)
            #pragma unroll
            for (int x = 0; x < 4; ++x)
                acc[y][x] += av[x] * bv[y];
    }

    float* __restrict__ gp = g_gram + b * RR * RR;
    #pragma unroll
    for (int y = 0; y < 4; ++y)
        #pragma unroll
        for (int x = 0; x < 4; ++x)
            gp[(tj * 4 + y) * RR + (ti * 4 + x)] = acc[y][x];
}

// ---------------------------------------------------------------------------
// Stage 4: deterministic final combine.
// total = mean_{q,r} log(density+eps)  +  sum_{i!=j} cov_ij^2
// ---------------------------------------------------------------------------
__global__ void final_kernel(float* __restrict__ out) {
    __shared__ float red[256];
    const int tid = threadIdx.x;  // 256 threads

    float es = 0.f;
    for (int i = tid; i < QT * RR; i += 256) es += g_ent_partial[i];

    float cs = 0.f;
    for (int p = tid; p < RR * RR; p += 256) {
        const int i = p & (RR - 1);
        const int j = p >> 6;
        float g = 0.f;
        #pragma unroll 4
        for (int b = 0; b < CB; ++b) g += g_gram[b * RR * RR + p];
        if (i != j) {
            const float c = g * (1.0f / (BB - 1));
            cs += c * c;
        }
    }

    red[tid] = es * (1.0f / (float)(BB * RR)) + cs;
    __syncthreads();
    for (int o = 128; o > 0; o >>= 1) {
        if (tid < o) red[tid] += red[tid + o];
        __syncthreads();
    }
    if (tid == 0) out[0] = red[0];
}

// ---------------------------------------------------------------------------
extern "C" void kernel_launch(void* const* d_in, const int* in_sizes, int n_in,
                              void* d_out, int out_size) {
    const float* act = (const float*)d_in[0];
    float* out = (float*)d_out;
    (void)in_sizes; (void)n_in; (void)out_size;

    stats_kernel<<<RR, 256>>>(act);
    kde_kernel<<<dim3(QT, RR), QTH>>>();
    cov_kernel<<<CB, 256>>>(act);
    final_kernel<<<1, 256>>>(out);
}

// round 4
// speedup vs baseline: 1.5979x; 1.5979x over previous
#include <cuda_runtime.h>
#include <math.h>

// Problem constants
#define BB 2048     // batch (samples == queries)
#define RR 64       // receptors
#define QT 16       // query tiles for KDE kernel
#define QTH 128     // threads per KDE block (queries per tile)
#define CB 32       // row-chunks for covariance Gram
#define CROWS 64    // rows per covariance chunk (CB*CROWS == BB)
#define GRB 64      // gram-reduce blocks

// -------- device scratch (static: no allocations allowed) --------
__device__ float g_scaled[RR * BB];      // column-major, value * invh * sqrt(0.5*log2e)
__device__ float g_dnorm[RR];            // invh / (B * sqrt(2*pi))
__device__ float g_mean[RR];
__device__ float g_ent_partial[QT * RR]; // per-(qtile, r) sum of log(density+eps)
__device__ float g_gram[CB * RR * RR];   // partial centered Gram per row-chunk
__device__ float g_cov_partial[GRB];     // per-block sum of squared off-diag cov

// Hardware exp2: single MUFU.EX2, flush-to-zero on tiny results (harmless here).
__device__ __forceinline__ float ex2(float x) {
    float y;
    asm("ex2.approx.ftz.f32 %0, %1;" : "=f"(y) : "f"(x));
    return y;
}

// ---------------------------------------------------------------------------
// Stage 1: per-column mean, std (ddof=1), bandwidth h; write scaled column-
// major copy of activity so the KDE inner loop is FADD+FMUL+EX2+FADD only.
// ---------------------------------------------------------------------------
__global__ void stats_kernel(const float* __restrict__ act) {
    __shared__ float sh[BB];
    __shared__ float red[256];
    const int r = blockIdx.x;
    const int tid = threadIdx.x;   // 256 threads

    float s = 0.f;
    for (int i = tid; i < BB; i += 256) {
        float v = act[i * RR + r];
        sh[i] = v;
        s += v;
    }
    red[tid] = s;
    __syncthreads();
    for (int o = 128; o > 0; o >>= 1) {
        if (tid < o) red[tid] += red[tid + o];
        __syncthreads();
    }
    const float mean = red[0] * (1.0f / BB);
    __syncthreads();

    float ss = 0.f;
    for (int i = tid; i < BB; i += 256) {
        float d = sh[i] - mean;
        ss += d * d;
    }
    red[tid] = ss;
    __syncthreads();
    for (int o = 128; o > 0; o >>= 1) {
        if (tid < o) red[tid] += red[tid + o];
        __syncthreads();
    }
    const float var  = red[0] * (1.0f / (BB - 1));
    const float stdv = sqrtf(var);
    // BANDWIDTH_FACTOR * std * B^(-0.2);  2048^(-0.2) = 0.21763764
    const float h    = fmaxf(1.06f * stdv * 0.21763764f, 1e-4f);
    const float invh = 1.0f / h;

    // sqrt(0.5 * log2(e)) so exp(-0.5*u^2) == 2^{-(u')^2} with u' = u*KS
    const float KS = 0.84932184f;
    const float k  = invh * KS;
    for (int i = tid; i < BB; i += 256)
        g_scaled[r * BB + i] = sh[i] * k;

    if (tid == 0) {
        g_dnorm[r] = invh * (1.0f / (2048.0f * 2.5066282746310002f)); // invh/(B*sqrt(2pi))
        g_mean[r]  = mean;
    }
}

// ---------------------------------------------------------------------------
// Stage 2: KDE densities + per-block sum of log(density + eps).
// grid (QT, RR), QTH threads; each thread owns one query, loops all samples
// from shared (broadcast reads). MUFU-bound by design.
// ---------------------------------------------------------------------------
__global__ void kde_kernel() {
    __shared__ float sh[BB];
    __shared__ float red[QTH];
    const int r   = blockIdx.y;
    const int qt  = blockIdx.x;
    const int tid = threadIdx.x;  // QTH = 128

    const float* __restrict__ col = g_scaled + r * BB;
    for (int i = tid; i < BB; i += QTH) sh[i] = col[i];
    __syncthreads();

    const int   q  = qt * QTH + tid;
    const float aq = sh[q];

    float a0 = 0.f, a1 = 0.f, a2 = 0.f, a3 = 0.f;
    float a4 = 0.f, a5 = 0.f, a6 = 0.f, a7 = 0.f;

    const float4* __restrict__ s4 = reinterpret_cast<const float4*>(sh);
    #pragma unroll 1
    for (int c = 0; c < BB / 8; ++c) {
        const float4 v0 = s4[2 * c + 0];
        const float4 v1 = s4[2 * c + 1];
        float u;
        u = aq - v0.x; a0 += ex2(-u * u);
        u = aq - v0.y; a1 += ex2(-u * u);
        u = aq - v0.z; a2 += ex2(-u * u);
        u = aq - v0.w; a3 += ex2(-u * u);
        u = aq - v1.x; a4 += ex2(-u * u);
        u = aq - v1.y; a5 += ex2(-u * u);
        u = aq - v1.z; a6 += ex2(-u * u);
        u = aq - v1.w; a7 += ex2(-u * u);
    }
    const float acc  = ((a0 + a1) + (a2 + a3)) + ((a4 + a5) + (a6 + a7));
    const float dens = acc * g_dnorm[r];
    const float lg   = logf(dens + 1e-8f);

    red[tid] = lg;
    __syncthreads();
    for (int o = QTH / 2; o > 0; o >>= 1) {
        if (tid < o) red[tid] += red[tid + o];
        __syncthreads();
    }
    if (tid == 0) g_ent_partial[qt * RR + r] = red[0];
}

// ---------------------------------------------------------------------------
// Stage 3: partial centered Gram (covariance numerator), tiled over rows.
// Each block handles CROWS rows; 16x16 threads each produce a 4x4 output tile.
// ---------------------------------------------------------------------------
__global__ void cov_kernel(const float* __restrict__ act) {
    __shared__ float sh[CROWS * RR];   // centered row tile: 64 x 64
    __shared__ float shm[RR];
    const int b   = blockIdx.x;
    const int tid = threadIdx.x;       // 256 threads

    if (tid < RR) shm[tid] = g_mean[tid];
    __syncthreads();

    const int base = b * CROWS * RR;
    for (int i = tid; i < CROWS * RR; i += 256)
        sh[i] = act[base + i] - shm[i & (RR - 1)];
    __syncthreads();

    const int ti = tid & 15;   // column-group i
    const int tj = tid >> 4;   // column-group j
    float acc[4][4];
    #pragma unroll
    for (int y = 0; y < 4; ++y)
        #pragma unroll
        for (int x = 0; x < 4; ++x) acc[y][x] = 0.f;

    const float4* __restrict__ s4 = reinterpret_cast<const float4*>(sh);
    for (int s = 0; s < CROWS; ++s) {
        const float4 ai = s4[s * 16 + ti];
        const float4 aj = s4[s * 16 + tj];
        const float av[4] = { ai.x, ai.y, ai.z, ai.w };
        const float bv[4] = { aj.x, aj.y, aj.z, aj.w };
        #pragma unroll
        for (int y = 0; y < 4; ++y)
            #pragma unroll
            for (int x = 0; x < 4; ++x)
                acc[y][x] += av[x] * bv[y];
    }

    float* __restrict__ gp = g_gram + b * RR * RR;
    #pragma unroll
    for (int y = 0; y < 4; ++y)
        #pragma unroll
        for (int x = 0; x < 4; ++x)
            gp[(tj * 4 + y) * RR + (ti * 4 + x)] = acc[y][x];
}

// ---------------------------------------------------------------------------
// Stage 3b: parallel reduction of the CB partial Grams.
// grid=GRB(64) blocks x 64 threads; thread owns one (i,j) cell: sums 32
// partials (fully unrolled -> MLP=32, latency hidden), squares off-diagonal,
// block-reduces, writes one scalar per block. Deterministic tree order.
// ---------------------------------------------------------------------------
__global__ void gram_reduce_kernel() {
    __shared__ float red[64];
    const int tid = threadIdx.x;                 // 64 threads
    const int p   = blockIdx.x * 64 + tid;       // cell index in 64x64
    const int i   = p & (RR - 1);
    const int j   = p >> 6;

    float g = 0.f;
    #pragma unroll
    for (int b = 0; b < CB; ++b) g += g_gram[b * RR * RR + p];

    float cs = 0.f;
    if (i != j) {
        const float c = g * (1.0f / (BB - 1));
        cs = c * c;
    }
    red[tid] = cs;
    __syncthreads();
    for (int o = 32; o > 0; o >>= 1) {
        if (tid < o) red[tid] += red[tid + o];
        __syncthreads();
    }
    if (tid == 0) g_cov_partial[blockIdx.x] = red[0];
}

// ---------------------------------------------------------------------------
// Stage 4: deterministic final combine (tiny: 1024 + 64 floats).
// total = mean_{q,r} log(density+eps)  +  sum_{i!=j} cov_ij^2
// ---------------------------------------------------------------------------
__global__ void final_kernel(float* __restrict__ out) {
    __shared__ float red[256];
    const int tid = threadIdx.x;  // 256 threads

    float es = 0.f;
    #pragma unroll 4
    for (int i = tid; i < QT * RR; i += 256) es += g_ent_partial[i];

    float cs = 0.f;
    if (tid < GRB) cs = g_cov_partial[tid];

    red[tid] = es * (1.0f / (float)(BB * RR)) + cs;
    __syncthreads();
    for (int o = 128; o > 0; o >>= 1) {
        if (tid < o) red[tid] += red[tid + o];
        __syncthreads();
    }
    if (tid == 0) out[0] = red[0];
}

// ---------------------------------------------------------------------------
extern "C" void kernel_launch(void* const* d_in, const int* in_sizes, int n_in,
                              void* d_out, int out_size) {
    const float* act = (const float*)d_in[0];
    float* out = (float*)d_out;
    (void)in_sizes; (void)n_in; (void)out_size;

    stats_kernel<<<RR, 256>>>(act);
    kde_kernel<<<dim3(QT, RR), QTH>>>();
    cov_kernel<<<CB, 256>>>(act);
    gram_reduce_kernel<<<GRB, 64>>>();
    final_kernel<<<1, 256>>>(out);
}

// round 5
// speedup vs baseline: 2.3031x; 1.4413x over previous
#include <cuda_runtime.h>
#include <math.h>

// Problem constants
#define BB 2048     // batch (samples == queries)
#define RR 64       // receptors
#define TILES 16    // BB / 128
#define NPAIRS 136  // TILES*(TILES+1)/2
#define QT 16       // query tiles for logsum kernel
#define CB 32       // row-chunks for covariance Gram
#define CROWS 64    // rows per covariance chunk (CB*CROWS == BB)
#define GRB 64      // gram-reduce blocks

// -------- device scratch (static: no allocations allowed) --------
__device__ float g_scaled[RR * BB];        // column-major, value * invh * sqrt(0.5*log2e)
__device__ float g_dnorm[RR];              // invh / (B * sqrt(2*pi))
__device__ float g_mean[RR];
__device__ float g_part[TILES * RR * BB];  // [slot][r][q] density partial sums (8MB)
__device__ float g_ent_partial[QT * RR];   // per-(qtile, r) sum of log(density+eps)
__device__ float g_gram[CB * RR * RR];     // partial centered Gram per row-chunk
__device__ float g_cov_partial[GRB];       // per-block sum of squared off-diag cov

// Hardware exp2: single MUFU.EX2 (ftz on tiny results — harmless here).
__device__ __forceinline__ float ex2(float x) {
    float y;
    asm("ex2.approx.ftz.f32 %0, %1;" : "=f"(y) : "f"(x));
    return y;
}

// ---------------------------------------------------------------------------
// Stage 1: per-column mean, std (ddof=1), bandwidth h; write scaled column-
// major copy of activity so the KDE inner loop is FADD+FMUL+EX2+FADD only.
// ---------------------------------------------------------------------------
__global__ void stats_kernel(const float* __restrict__ act) {
    __shared__ float sh[BB];
    __shared__ float red[256];
    const int r = blockIdx.x;
    const int tid = threadIdx.x;   // 256 threads

    float s = 0.f;
    for (int i = tid; i < BB; i += 256) {
        float v = act[i * RR + r];
        sh[i] = v;
        s += v;
    }
    red[tid] = s;
    __syncthreads();
    for (int o = 128; o > 0; o >>= 1) {
        if (tid < o) red[tid] += red[tid + o];
        __syncthreads();
    }
    const float mean = red[0] * (1.0f / BB);
    __syncthreads();

    float ss = 0.f;
    for (int i = tid; i < BB; i += 256) {
        float d = sh[i] - mean;
        ss += d * d;
    }
    red[tid] = ss;
    __syncthreads();
    for (int o = 128; o > 0; o >>= 1) {
        if (tid < o) red[tid] += red[tid + o];
        __syncthreads();
    }
    const float var  = red[0] * (1.0f / (BB - 1));
    const float stdv = sqrtf(var);
    // BANDWIDTH_FACTOR * std * B^(-0.2);  2048^(-0.2) = 0.21763764
    const float h    = fmaxf(1.06f * stdv * 0.21763764f, 1e-4f);
    const float invh = 1.0f / h;

    // sqrt(0.5 * log2(e)) so exp(-0.5*u^2) == 2^{-(u')^2} with u' = u*KS
    const float KS = 0.84932184f;
    const float k  = invh * KS;
    for (int i = tid; i < BB; i += 256)
        g_scaled[r * BB + i] = sh[i] * k;

    if (tid == 0) {
        g_dnorm[r] = invh * (1.0f / (2048.0f * 2.5066282746310002f)); // invh/(B*sqrt(2pi))
        g_mean[r]  = mean;
    }
}

// ---------------------------------------------------------------------------
// Stage 2: symmetric KDE. Block = (tile-pair p, receptor r), 128 threads.
// Each lane owns 4 columns of tile J in registers (sv + col accumulator ca);
// (query value, row accumulator) rotates across the 32 lanes via SHFL.
// 32 steps x 4 cols = 128 columns per query; each warp handles 32 queries.
// Off-diagonal pairs (I<J): each exp serves both a row (tile-I query) and a
// column (tile-J query) density. Diagonal: row accumulation only.
// No atomics; every g_part cell written by exactly one block (slot-unique).
// ---------------------------------------------------------------------------
__global__ void kde_sym_kernel() {
    const int r = blockIdx.y;
    // map linear pair index -> (I, J), I <= J
    int I = 0, rem = blockIdx.x;
    while (rem >= TILES - I) { rem -= TILES - I; ++I; }
    const int J = I + rem;

    const int tid  = threadIdx.x;   // 128
    const int lane = tid & 31;
    const int w    = tid >> 5;

    const float* __restrict__ col = g_scaled + r * BB;

    // lane's 4 columns from tile J (registers for the whole loop)
    const float4 sv = reinterpret_cast<const float4*>(col + J * 128)[lane];
    // this thread's query from tile I
    float aqc  = col[I * 128 + tid];
    float rowc = 0.f;
    float4 ca  = make_float4(0.f, 0.f, 0.f, 0.f);

    const unsigned FULL = 0xFFFFFFFFu;

    if (I != J) {
        #pragma unroll 8
        for (int m = 0; m < 32; ++m) {
            float u, v0, v1, v2, v3;
            u = aqc - sv.x; v0 = ex2(-u * u);
            u = aqc - sv.y; v1 = ex2(-u * u);
            u = aqc - sv.z; v2 = ex2(-u * u);
            u = aqc - sv.w; v3 = ex2(-u * u);
            ca.x += v0; ca.y += v1; ca.z += v2; ca.w += v3;
            rowc += (v0 + v1) + (v2 + v3);
            // rotate (query, row-acc) to the next lane; after 32 steps it is home
            aqc  = __shfl_sync(FULL, aqc,  (lane + 1) & 31);
            rowc = __shfl_sync(FULL, rowc, (lane + 1) & 31);
        }

        // merge per-warp column sums across the 4 warps
        __shared__ float shc[4][128];
        reinterpret_cast<float4*>(shc[w])[lane] = ca;
        __syncthreads();
        const float ct = shc[0][tid] + shc[1][tid] + shc[2][tid] + shc[3][tid];

        // column sums -> densities of tile-J queries, slot I
        g_part[I * (RR * BB) + r * BB + J * 128 + tid] = ct;
        // row sums -> densities of tile-I queries, slot J
        g_part[J * (RR * BB) + r * BB + I * 128 + tid] = rowc;
    } else {
        #pragma unroll 8
        for (int m = 0; m < 32; ++m) {
            float u, v0, v1, v2, v3;
            u = aqc - sv.x; v0 = ex2(-u * u);
            u = aqc - sv.y; v1 = ex2(-u * u);
            u = aqc - sv.z; v2 = ex2(-u * u);
            u = aqc - sv.w; v3 = ex2(-u * u);
            rowc += (v0 + v1) + (v2 + v3);
            aqc  = __shfl_sync(FULL, aqc,  (lane + 1) & 31);
            rowc = __shfl_sync(FULL, rowc, (lane + 1) & 31);
        }
        g_part[I * (RR * BB) + r * BB + I * 128 + tid] = rowc;
    }
}

// ---------------------------------------------------------------------------
// Stage 2b: fold the 16 density partial slots, take log, reduce per block.
// ---------------------------------------------------------------------------
__global__ void logsum_kernel() {
    __shared__ float red[128];
    const int r   = blockIdx.y;
    const int qt  = blockIdx.x;
    const int tid = threadIdx.x;   // 128
    const int q   = qt * 128 + tid;

    float s = 0.f;
    #pragma unroll
    for (int slot = 0; slot < TILES; ++slot)
        s += g_part[slot * (RR * BB) + r * BB + q];

    const float dens = s * g_dnorm[r];
    const float lg   = logf(dens + 1e-8f);

    red[tid] = lg;
    __syncthreads();
    for (int o = 64; o > 0; o >>= 1) {
        if (tid < o) red[tid] += red[tid + o];
        __syncthreads();
    }
    if (tid == 0) g_ent_partial[qt * RR + r] = red[0];
}

// ---------------------------------------------------------------------------
// Stage 3: partial centered Gram (covariance numerator), tiled over rows.
// ---------------------------------------------------------------------------
__global__ void cov_kernel(const float* __restrict__ act) {
    __shared__ float sh[CROWS * RR];   // centered row tile: 64 x 64
    __shared__ float shm[RR];
    const int b   = blockIdx.x;
    const int tid = threadIdx.x;       // 256 threads

    if (tid < RR) shm[tid] = g_mean[tid];
    __syncthreads();

    const int base = b * CROWS * RR;
    for (int i = tid; i < CROWS * RR; i += 256)
        sh[i] = act[base + i] - shm[i & (RR - 1)];
    __syncthreads();

    const int ti = tid & 15;   // column-group i
    const int tj = tid >> 4;   // column-group j
    float acc[4][4];
    #pragma unroll
    for (int y = 0; y < 4; ++y)
        #pragma unroll
        for (int x = 0; x < 4; ++x) acc[y][x] = 0.f;

    const float4* __restrict__ s4 = reinterpret_cast<const float4*>(sh);
    for (int s = 0; s < CROWS; ++s) {
        const float4 ai = s4[s * 16 + ti];
        const float4 aj = s4[s * 16 + tj];
        const float av[4] = { ai.x, ai.y, ai.z, ai.w };
        const float bv[4] = { aj.x, aj.y, aj.z, aj.w };
        #pragma unroll
        for (int y = 0; y < 4; ++y)
            #pragma unroll
            for (int x = 0; x < 4; ++x)
                acc[y][x] += av[x] * bv[y];
    }

    float* __restrict__ gp = g_gram + b * RR * RR;
    #pragma unroll
    for (int y = 0; y < 4; ++y)
        #pragma unroll
        for (int x = 0; x < 4; ++x)
            gp[(tj * 4 + y) * RR + (ti * 4 + x)] = acc[y][x];
}

// ---------------------------------------------------------------------------
// Stage 3b: parallel reduction of the CB partial Grams (deterministic tree).
// ---------------------------------------------------------------------------
__global__ void gram_reduce_kernel() {
    __shared__ float red[64];
    const int tid = threadIdx.x;                 // 64 threads
    const int p   = blockIdx.x * 64 + tid;       // cell index in 64x64
    const int i   = p & (RR - 1);
    const int j   = p >> 6;

    float g = 0.f;
    #pragma unroll
    for (int b = 0; b < CB; ++b) g += g_gram[b * RR * RR + p];

    float cs = 0.f;
    if (i != j) {
        const float c = g * (1.0f / (BB - 1));
        cs = c * c;
    }
    red[tid] = cs;
    __syncthreads();
    for (int o = 32; o > 0; o >>= 1) {
        if (tid < o) red[tid] += red[tid + o];
        __syncthreads();
    }
    if (tid == 0) g_cov_partial[blockIdx.x] = red[0];
}

// ---------------------------------------------------------------------------
// Stage 4: deterministic final combine (tiny: 1024 + 64 floats).
// ---------------------------------------------------------------------------
__global__ void final_kernel(float* __restrict__ out) {
    __shared__ float red[256];
    const int tid = threadIdx.x;  // 256 threads

    float es = 0.f;
    #pragma unroll 4
    for (int i = tid; i < QT * RR; i += 256) es += g_ent_partial[i];

    float cs = 0.f;
    if (tid < GRB) cs = g_cov_partial[tid];

    red[tid] = es * (1.0f / (float)(BB * RR)) + cs;
    __syncthreads();
    for (int o = 128; o > 0; o >>= 1) {
        if (tid < o) red[tid] += red[tid + o];
        __syncthreads();
    }
    if (tid == 0) out[0] = red[0];
}

// ---------------------------------------------------------------------------
extern "C" void kernel_launch(void* const* d_in, const int* in_sizes, int n_in,
                              void* d_out, int out_size) {
    const float* act = (const float*)d_in[0];
    float* out = (float*)d_out;
    (void)in_sizes; (void)n_in; (void)out_size;

    stats_kernel<<<RR, 256>>>(act);
    kde_sym_kernel<<<dim3(NPAIRS, RR), 128>>>();
    logsum_kernel<<<dim3(QT, RR), 128>>>();
    cov_kernel<<<CB, 256>>>(act);
    gram_reduce_kernel<<<GRB, 64>>>();
    final_kernel<<<1, 256>>>(out);
}

// round 6
// speedup vs baseline: 2.4250x; 1.0529x over previous
#include <cuda_runtime.h>
#include <math.h>

// Problem constants
#define BB 2048     // batch (samples == queries)
#define RR 64       // receptors
#define TILES 16    // BB / 128
#define NPAIRS 136  // TILES*(TILES+1)/2
#define QT 16       // query tiles for logsum
#define CB 128      // row-chunks for covariance Gram
#define CROWS 16    // rows per covariance chunk (CB*CROWS == BB)
#define GRB 32      // gram-reduce blocks (32 x 128 threads = 4096 cells)

// -------- device scratch (static: no allocations allowed) --------
__device__ float g_scaled[RR * BB];        // column-major, value * invh * sqrt(0.5*log2e)
__device__ float g_dnorm[RR];              // invh / (B * sqrt(2*pi))
__device__ float g_mean[RR];
__device__ float g_part[TILES * RR * BB];  // [slot][r][q] density partial sums (8MB)
__device__ float g_ent_partial[QT * RR];   // per-(qtile, r) sum of log(density+eps)
__device__ float g_gram[CB * RR * RR];     // RAW (uncentered) Gram partials (2MB)
__device__ float g_cov_partial[GRB];       // per-block sum of squared off-diag cov

// Hardware exp2: single MUFU.EX2 (ftz on tiny results — harmless here).
__device__ __forceinline__ float ex2(float x) {
    float y;
    asm("ex2.approx.ftz.f32 %0, %1;" : "=f"(y) : "f"(x));
    return y;
}

// ---------------------------------------------------------------------------
// Stage 1 (fused): blocks [0, RR)      -> per-column stats + scaled copy
//                  blocks [RR, RR+CB)  -> raw Gram partial over 16 rows
// The two halves are independent (both read only `act`); mean correction for
// the Gram is applied later in reduce_kernel.
// ---------------------------------------------------------------------------
__global__ void stats_cov_kernel(const float* __restrict__ act) {
    const int tid = threadIdx.x;   // 256 threads

    if (blockIdx.x < RR) {
        // ---------------- stats half ----------------
        __shared__ float sh[BB];
        __shared__ float red[256];
        const int r = blockIdx.x;

        float s = 0.f;
        for (int i = tid; i < BB; i += 256) {
            float v = act[i * RR + r];
            sh[i] = v;
            s += v;
        }
        red[tid] = s;
        __syncthreads();
        for (int o = 128; o > 0; o >>= 1) {
            if (tid < o) red[tid] += red[tid + o];
            __syncthreads();
        }
        const float mean = red[0] * (1.0f / BB);
        __syncthreads();

        float ss = 0.f;
        for (int i = tid; i < BB; i += 256) {
            float d = sh[i] - mean;
            ss += d * d;
        }
        red[tid] = ss;
        __syncthreads();
        for (int o = 128; o > 0; o >>= 1) {
            if (tid < o) red[tid] += red[tid + o];
            __syncthreads();
        }
        const float var  = red[0] * (1.0f / (BB - 1));
        const float stdv = sqrtf(var);
        // BANDWIDTH_FACTOR * std * B^(-0.2);  2048^(-0.2) = 0.21763764
        const float h    = fmaxf(1.06f * stdv * 0.21763764f, 1e-4f);
        const float invh = 1.0f / h;

        // sqrt(0.5 * log2(e)) so exp(-0.5*u^2) == 2^{-(u')^2}
        const float KS = 0.84932184f;
        const float k  = invh * KS;
        for (int i = tid; i < BB; i += 256)
            g_scaled[r * BB + i] = sh[i] * k;

        if (tid == 0) {
            g_dnorm[r] = invh * (1.0f / (2048.0f * 2.5066282746310002f));
            g_mean[r]  = mean;
        }
    } else {
        // ---------------- raw Gram half ----------------
        __shared__ float ch[CROWS * RR];   // 16 x 64 raw rows (4KB)
        const int b = blockIdx.x - RR;     // 0..CB-1

        // coalesced float4 load: 256 threads x 1 float4 = 1024 floats
        reinterpret_cast<float4*>(ch)[tid] =
            reinterpret_cast<const float4*>(act + b * CROWS * RR)[tid];
        __syncthreads();

        const int ti = tid & 15;   // column-group i
        const int tj = tid >> 4;   // column-group j
        float acc[4][4];
        #pragma unroll
        for (int y = 0; y < 4; ++y)
            #pragma unroll
            for (int x = 0; x < 4; ++x) acc[y][x] = 0.f;

        const float4* __restrict__ s4 = reinterpret_cast<const float4*>(ch);
        #pragma unroll
        for (int s = 0; s < CROWS; ++s) {
            const float4 ai = s4[s * 16 + ti];
            const float4 aj = s4[s * 16 + tj];
            const float av[4] = { ai.x, ai.y, ai.z, ai.w };
            const float bv[4] = { aj.x, aj.y, aj.z, aj.w };
            #pragma unroll
            for (int y = 0; y < 4; ++y)
                #pragma unroll
                for (int x = 0; x < 4; ++x)
                    acc[y][x] += av[x] * bv[y];
        }

        float* __restrict__ gp = g_gram + b * RR * RR;
        #pragma unroll
        for (int y = 0; y < 4; ++y)
            #pragma unroll
            for (int x = 0; x < 4; ++x)
                gp[(tj * 4 + y) * RR + (ti * 4 + x)] = acc[y][x];
    }
}

// ---------------------------------------------------------------------------
// Stage 2: symmetric KDE. Block = (tile-pair p, receptor r), 128 threads.
// Each lane owns 4 columns of tile J in registers; (query, row accumulator)
// rotates across the 32 lanes via SHFL. Off-diagonal pairs: each exp serves
// both a row (tile-I) and a column (tile-J) density. No atomics; every
// g_part cell is written by exactly one block.
// ---------------------------------------------------------------------------
__global__ void kde_sym_kernel() {
    const int r = blockIdx.y;
    // map linear pair index -> (I, J), I <= J
    int I = 0, rem = blockIdx.x;
    while (rem >= TILES - I) { rem -= TILES - I; ++I; }
    const int J = I + rem;

    const int tid  = threadIdx.x;   // 128
    const int lane = tid & 31;
    const int w    = tid >> 5;

    const float* __restrict__ col = g_scaled + r * BB;

    const float4 sv = reinterpret_cast<const float4*>(col + J * 128)[lane];
    float aqc  = col[I * 128 + tid];
    float rowc = 0.f;
    float4 ca  = make_float4(0.f, 0.f, 0.f, 0.f);

    const unsigned FULL = 0xFFFFFFFFu;

    if (I != J) {
        #pragma unroll 8
        for (int m = 0; m < 32; ++m) {
            float u, v0, v1, v2, v3;
            u = aqc - sv.x; v0 = ex2(-u * u);
            u = aqc - sv.y; v1 = ex2(-u * u);
            u = aqc - sv.z; v2 = ex2(-u * u);
            u = aqc - sv.w; v3 = ex2(-u * u);
            ca.x += v0; ca.y += v1; ca.z += v2; ca.w += v3;
            rowc += (v0 + v1) + (v2 + v3);
            aqc  = __shfl_sync(FULL, aqc,  (lane + 1) & 31);
            rowc = __shfl_sync(FULL, rowc, (lane + 1) & 31);
        }

        __shared__ float shc[4][128];
        reinterpret_cast<float4*>(shc[w])[lane] = ca;
        __syncthreads();
        const float ct = shc[0][tid] + shc[1][tid] + shc[2][tid] + shc[3][tid];

        g_part[I * (RR * BB) + r * BB + J * 128 + tid] = ct;    // tile-J densities
        g_part[J * (RR * BB) + r * BB + I * 128 + tid] = rowc;  // tile-I densities
    } else {
        #pragma unroll 8
        for (int m = 0; m < 32; ++m) {
            float u, v0, v1, v2, v3;
            u = aqc - sv.x; v0 = ex2(-u * u);
            u = aqc - sv.y; v1 = ex2(-u * u);
            u = aqc - sv.z; v2 = ex2(-u * u);
            u = aqc - sv.w; v3 = ex2(-u * u);
            rowc += (v0 + v1) + (v2 + v3);
            aqc  = __shfl_sync(FULL, aqc,  (lane + 1) & 31);
            rowc = __shfl_sync(FULL, rowc, (lane + 1) & 31);
        }
        g_part[I * (RR * BB) + r * BB + I * 128 + tid] = rowc;
    }
}

// ---------------------------------------------------------------------------
// Stage 3 (fused): blocks [0, QT*RR)            -> logsum of densities
//                  blocks [QT*RR, QT*RR + GRB)  -> Gram fold + mean-correct +
//                                                  off-diag square-sum
// The two halves are independent. 128 threads each.
// ---------------------------------------------------------------------------
__global__ void reduce_kernel() {
    __shared__ float red[128];
    const int tid = threadIdx.x;   // 128

    if (blockIdx.x < QT * RR) {
        // ---------------- logsum half ----------------
        const int r  = blockIdx.x >> 4;
        const int qt = blockIdx.x & 15;
        const int q  = qt * 128 + tid;

        float s = 0.f;
        #pragma unroll
        for (int slot = 0; slot < TILES; ++slot)
            s += g_part[slot * (RR * BB) + r * BB + q];

        const float dens = s * g_dnorm[r];
        red[tid] = logf(dens + 1e-8f);
        __syncthreads();
        for (int o = 64; o > 0; o >>= 1) {
            if (tid < o) red[tid] += red[tid + o];
            __syncthreads();
        }
        if (tid == 0) g_ent_partial[qt * RR + r] = red[0];
    } else {
        // ---------------- Gram-reduce half ----------------
        const int gb = blockIdx.x - QT * RR;   // 0..GRB-1
        const int p  = gb * 128 + tid;         // cell in 64x64
        const int i  = p & (RR - 1);
        const int j  = p >> 6;

        float g = 0.f;
        #pragma unroll 16
        for (int b = 0; b < CB; ++b) g += g_gram[b * RR * RR + p];

        // centered Gram: sum((x_i - m_i)(x_j - m_j)) = raw - B*m_i*m_j
        g -= (float)BB * g_mean[i] * g_mean[j];

        float cs = 0.f;
        if (i != j) {
            const float c = g * (1.0f / (BB - 1));
            cs = c * c;
        }
        red[tid] = cs;
        __syncthreads();
        for (int o = 64; o > 0; o >>= 1) {
            if (tid < o) red[tid] += red[tid + o];
            __syncthreads();
        }
        if (tid == 0) g_cov_partial[gb] = red[0];
    }
}

// ---------------------------------------------------------------------------
// Stage 4: deterministic final combine (tiny: 1024 + 32 floats).
// ---------------------------------------------------------------------------
__global__ void final_kernel(float* __restrict__ out) {
    __shared__ float red[256];
    const int tid = threadIdx.x;  // 256 threads

    float es = 0.f;
    #pragma unroll 4
    for (int i = tid; i < QT * RR; i += 256) es += g_ent_partial[i];

    float cs = 0.f;
    if (tid < GRB) cs = g_cov_partial[tid];

    red[tid] = es * (1.0f / (float)(BB * RR)) + cs;
    __syncthreads();
    for (int o = 128; o > 0; o >>= 1) {
        if (tid < o) red[tid] += red[tid + o];
        __syncthreads();
    }
    if (tid == 0) out[0] = red[0];
}

// ---------------------------------------------------------------------------
extern "C" void kernel_launch(void* const* d_in, const int* in_sizes, int n_in,
                              void* d_out, int out_size) {
    const float* act = (const float*)d_in[0];
    float* out = (float*)d_out;
    (void)in_sizes; (void)n_in; (void)out_size;

    stats_cov_kernel<<<RR + CB, 256>>>(act);
    kde_sym_kernel<<<dim3(NPAIRS, RR), 128>>>();
    reduce_kernel<<<QT * RR + GRB, 128>>>();
    final_kernel<<<1, 256>>>(out);
}